// round 14
// baseline (speedup 1.0000x reference)
#include <cuda_runtime.h>
#include <cuda_bf16.h>
#include <cstdint>
#include <math.h>

#define NB 16384
#define ND 256

static __device__ __nv_bfloat16 g_qh[NB * ND];  // normalized Q * log2(e)/T, bf16
static __device__ __nv_bfloat16 g_dh[NB * ND];  // normalized D, bf16
static __device__ float g_rowsum[NB];
static __device__ float g_colsum[NB];
static __device__ float g_diag[NB];             // exact fp32 diagonal logits

__device__ __forceinline__ uint32_t smem_u32(const void* p) {
    uint32_t a;
    asm("{ .reg .u64 t; cvta.to.shared.u64 t, %1; cvt.u32.u64 %0, t; }" : "=r"(a) : "l"(p));
    return a;
}
__device__ __forceinline__ float ex2_approx(float x) {
    float r; asm("ex2.approx.f32 %0, %1;" : "=f"(r) : "f"(x)); return r;
}
__device__ __forceinline__ uint32_t bf2_bits(__nv_bfloat162 v) {
    return *reinterpret_cast<uint32_t*>(&v);
}

// ---------------- prep: normalize q & d, exact diag, zero sums ----------------
// one warp handles TWO rows (row, row + NB/2): 8 independent 32B loads in
// flight up front (2x MLP vs one-row version), reductions interleaved.
__global__ void prep_kernel(const float* __restrict__ qin, const float* __restrict__ din,
                            float* __restrict__ out) {
    const float K = 1.4426950408889634f / 0.07f;  // log2(e)/T folded into Q
    int row0 = blockIdx.x * 8 + threadIdx.y;
    int row1 = row0 + NB / 2;
    int lane = threadIdx.x;

    const float4* qs0 = reinterpret_cast<const float4*>(qin + (size_t)row0 * ND);
    const float4* ds0 = reinterpret_cast<const float4*>(din + (size_t)row0 * ND);
    const float4* qs1 = reinterpret_cast<const float4*>(qin + (size_t)row1 * ND);
    const float4* ds1 = reinterpret_cast<const float4*>(din + (size_t)row1 * ND);

    // issue all 8 loads before any reduction work
    float4 a0 = qs0[2 * lane], a1 = qs0[2 * lane + 1];
    float4 b0 = ds0[2 * lane], b1 = ds0[2 * lane + 1];
    float4 c0 = qs1[2 * lane], c1 = qs1[2 * lane + 1];
    float4 e0 = ds1[2 * lane], e1 = ds1[2 * lane + 1];

    float sq0 = a0.x * a0.x + a0.y * a0.y + a0.z * a0.z + a0.w * a0.w
              + a1.x * a1.x + a1.y * a1.y + a1.z * a1.z + a1.w * a1.w;
    float sd0 = b0.x * b0.x + b0.y * b0.y + b0.z * b0.z + b0.w * b0.w
              + b1.x * b1.x + b1.y * b1.y + b1.z * b1.z + b1.w * b1.w;
    float dt0 = a0.x * b0.x + a0.y * b0.y + a0.z * b0.z + a0.w * b0.w
              + a1.x * b1.x + a1.y * b1.y + a1.z * b1.z + a1.w * b1.w;
    float sq1 = c0.x * c0.x + c0.y * c0.y + c0.z * c0.z + c0.w * c0.w
              + c1.x * c1.x + c1.y * c1.y + c1.z * c1.z + c1.w * c1.w;
    float sd1 = e0.x * e0.x + e0.y * e0.y + e0.z * e0.z + e0.w * e0.w
              + e1.x * e1.x + e1.y * e1.y + e1.z * e1.z + e1.w * e1.w;
    float dt1 = c0.x * e0.x + c0.y * e0.y + c0.z * e0.z + c0.w * e0.w
              + c1.x * e1.x + c1.y * e1.y + c1.z * e1.z + c1.w * e1.w;
#pragma unroll
    for (int o = 16; o > 0; o >>= 1) {
        sq0 += __shfl_xor_sync(0xFFFFFFFFu, sq0, o);
        sd0 += __shfl_xor_sync(0xFFFFFFFFu, sd0, o);
        dt0 += __shfl_xor_sync(0xFFFFFFFFu, dt0, o);
        sq1 += __shfl_xor_sync(0xFFFFFFFFu, sq1, o);
        sd1 += __shfl_xor_sync(0xFFFFFFFFu, sd1, o);
        dt1 += __shfl_xor_sync(0xFFFFFFFFu, dt1, o);
    }
    float nq0 = fmaxf(sqrtf(sq0), 1e-12f);
    float nd0 = fmaxf(sqrtf(sd0), 1e-12f);
    float nq1 = fmaxf(sqrtf(sq1), 1e-12f);
    float nd1 = fmaxf(sqrtf(sd1), 1e-12f);
    float iq0 = K / nq0, id0 = 1.0f / nd0;
    float iq1 = K / nq1, id1 = 1.0f / nd1;

    uint4 p;
    p.x = bf2_bits(__floats2bfloat162_rn(a0.x * iq0, a0.y * iq0));
    p.y = bf2_bits(__floats2bfloat162_rn(a0.z * iq0, a0.w * iq0));
    p.z = bf2_bits(__floats2bfloat162_rn(a1.x * iq0, a1.y * iq0));
    p.w = bf2_bits(__floats2bfloat162_rn(a1.z * iq0, a1.w * iq0));
    reinterpret_cast<uint4*>(g_qh + (size_t)row0 * ND)[lane] = p;
    p.x = bf2_bits(__floats2bfloat162_rn(b0.x * id0, b0.y * id0));
    p.y = bf2_bits(__floats2bfloat162_rn(b0.z * id0, b0.w * id0));
    p.z = bf2_bits(__floats2bfloat162_rn(b1.x * id0, b1.y * id0));
    p.w = bf2_bits(__floats2bfloat162_rn(b1.z * id0, b1.w * id0));
    reinterpret_cast<uint4*>(g_dh + (size_t)row0 * ND)[lane] = p;
    p.x = bf2_bits(__floats2bfloat162_rn(c0.x * iq1, c0.y * iq1));
    p.y = bf2_bits(__floats2bfloat162_rn(c0.z * iq1, c0.w * iq1));
    p.z = bf2_bits(__floats2bfloat162_rn(c1.x * iq1, c1.y * iq1));
    p.w = bf2_bits(__floats2bfloat162_rn(c1.z * iq1, c1.w * iq1));
    reinterpret_cast<uint4*>(g_qh + (size_t)row1 * ND)[lane] = p;
    p.x = bf2_bits(__floats2bfloat162_rn(e0.x * id1, e0.y * id1));
    p.y = bf2_bits(__floats2bfloat162_rn(e0.z * id1, e0.w * id1));
    p.z = bf2_bits(__floats2bfloat162_rn(e1.x * id1, e1.y * id1));
    p.w = bf2_bits(__floats2bfloat162_rn(e1.z * id1, e1.w * id1));
    reinterpret_cast<uint4*>(g_dh + (size_t)row1 * ND)[lane] = p;

    if (lane == 0) {
        g_diag[row0] = dt0 / (nq0 * nd0) * (1.0f / 0.07f);
        g_diag[row1] = dt1 / (nq1 * nd1) * (1.0f / 0.07f);
        g_rowsum[row0] = 0.0f; g_rowsum[row1] = 0.0f;
        g_colsum[row0] = 0.0f; g_colsum[row1] = 0.0f;
        if (row0 == 0) out[0] = 0.0f;
    }
}

// ---------------- fused mma.sync GEMM + exp2 + row/col sums ----------------
// CTA tile 128x128, K chunks of 64, 3-stage cp.async pipeline, one sync/chunk.
// All chunks: A-fragments prefetched for whole chunk, np-major B feed.
// Chunk 3 interleaves the epilogue (all-MUFU exp2) with the MMA stream.
#define STAGE_BYTES 32768
#define SMEM_DYN (3 * STAGE_BYTES)

__global__ void __launch_bounds__(256, 2) gemm_lse_kernel() {
    extern __shared__ char smem[];
    uint32_t sbase = smem_u32(smem);
    int tid = threadIdx.x;
    int wid = tid >> 5, lid = tid & 31;
    int wr = wid & 3, wc = wid >> 2;   // warp tile: rows wr*32..+32, cols wc*64..+64
    int bi = blockIdx.y * 128, bj = blockIdx.x * 128;

    // ---- loader per-thread constants (strength-reduced SW128) ----
    int r0 = tid >> 3;
    int kbl = (tid & 7) * 16;
    uint32_t soff0 = (uint32_t)(r0 * 128 + (kbl ^ ((r0 & 7) << 4)));
    const char* Ag = (const char*)(g_qh + (size_t)bi * ND) + r0 * 512 + kbl;
    const char* Bg = (const char*)(g_dh + (size_t)bj * ND) + r0 * 512 + kbl;

    auto load_chunk = [&](int c, int s) {
        uint32_t sA = sbase + s * STAGE_BYTES + soff0;
        const char* a = Ag + c * 128;
        const char* b = Bg + c * 128;
#pragma unroll
        for (int i = 0; i < 4; i++) {
            asm volatile("cp.async.cg.shared.global [%0], [%1], 16;"
                         :: "r"(sA + i * 4096), "l"(a + i * 16384));
            asm volatile("cp.async.cg.shared.global [%0], [%1], 16;"
                         :: "r"(sA + 16384 + i * 4096), "l"(b + i * 16384));
        }
        asm volatile("cp.async.commit_group;");
    };

    float acc[2][8][4];
#pragma unroll
    for (int mt = 0; mt < 2; mt++)
#pragma unroll
        for (int nt = 0; nt < 8; nt++)
#pragma unroll
            for (int j = 0; j < 4; j++) acc[mt][nt][j] = 0.0f;

    // ---- ldmatrix per-thread constants ----
    int fr = (lid & 7) + ((lid >> 3) & 1) * 8;
    uint32_t cswz = (uint32_t)((lid & 7) << 4);
    uint32_t hi16 = ((lid >> 4) & 1) * 16;
    uint32_t rbA[2], rbB[4];
#pragma unroll
    for (int mt = 0; mt < 2; mt++) rbA[mt] = (uint32_t)((wr * 32 + mt * 16 + fr) * 128);
#pragma unroll
    for (int np = 0; np < 4; np++) rbB[np] = (uint32_t)((wc * 64 + np * 16 + fr) * 128);

    // per-chunk body: prefetch all A frags, then np-major B feed + MMA
#define CHUNK_MMA(aS, bS) do {                                                    \
        uint32_t af[4][2][4];                                                     \
        _Pragma("unroll")                                                         \
        for (int ks = 0; ks < 4; ks++) {                                          \
            uint32_t kx = ((uint32_t)(ks * 32) + hi16) ^ cswz;                    \
            _Pragma("unroll")                                                     \
            for (int mt = 0; mt < 2; mt++)                                        \
                asm volatile("ldmatrix.sync.aligned.m8n8.x4.shared.b16 {%0,%1,%2,%3}, [%4];" \
                             : "=r"(af[ks][mt][0]), "=r"(af[ks][mt][1]),          \
                               "=r"(af[ks][mt][2]), "=r"(af[ks][mt][3])           \
                             : "r"((aS) + rbA[mt] + kx));                         \
        }                                                                         \
        _Pragma("unroll")                                                         \
        for (int np = 0; np < 4; np++) {                                          \
            _Pragma("unroll")                                                     \
            for (int ks = 0; ks < 4; ks++) {                                      \
                uint32_t kx = ((uint32_t)(ks * 32) + hi16) ^ cswz;                \
                uint32_t q0, q1, q2, q3;                                          \
                asm volatile("ldmatrix.sync.aligned.m8n8.x4.shared.b16 {%0,%1,%2,%3}, [%4];" \
                             : "=r"(q0), "=r"(q1), "=r"(q2), "=r"(q3)             \
                             : "r"((bS) + rbB[np] + kx));                         \
                _Pragma("unroll")                                                 \
                for (int mt = 0; mt < 2; mt++) {                                  \
                    asm volatile(                                                 \
                        "mma.sync.aligned.m16n8k16.row.col.f32.bf16.bf16.f32 "    \
                        "{%0,%1,%2,%3}, {%4,%5,%6,%7}, {%8,%9}, {%0,%1,%2,%3};"   \
                        : "+f"(acc[mt][2 * np][0]), "+f"(acc[mt][2 * np][1]),     \
                          "+f"(acc[mt][2 * np][2]), "+f"(acc[mt][2 * np][3])      \
                        : "r"(af[ks][mt][0]), "r"(af[ks][mt][1]),                 \
                          "r"(af[ks][mt][2]), "r"(af[ks][mt][3]),                 \
                          "r"(q0), "r"(q2));                                      \
                    asm volatile(                                                 \
                        "mma.sync.aligned.m16n8k16.row.col.f32.bf16.bf16.f32 "    \
                        "{%0,%1,%2,%3}, {%4,%5,%6,%7}, {%8,%9}, {%0,%1,%2,%3};"   \
                        : "+f"(acc[mt][2 * np + 1][0]), "+f"(acc[mt][2 * np + 1][1]), \
                          "+f"(acc[mt][2 * np + 1][2]), "+f"(acc[mt][2 * np + 1][3]) \
                        : "r"(af[ks][mt][0]), "r"(af[ks][mt][1]),                 \
                          "r"(af[ks][mt][2]), "r"(af[ks][mt][3]),                 \
                          "r"(q1), "r"(q3));                                      \
                }                                                                 \
            }                                                                     \
        }                                                                         \
    } while (0)

    // ---- prologue: fill 3 stages ----
    load_chunk(0, 0);
    load_chunk(1, 1);
    load_chunk(2, 2);

    // ---- chunks 0..2 ----
#pragma unroll
    for (int c = 0; c < 3; c++) {
        if (c == 0) { asm volatile("cp.async.wait_group 2;"); }
        else        { asm volatile("cp.async.wait_group 1;"); }
        __syncthreads();
        if (c == 1) load_chunk(3, 0);

        uint32_t aS = sbase + c * STAGE_BYTES;
        uint32_t bS = aS + 16384;
        CHUNK_MMA(aS, bS);
    }

    // ---- chunk 3: interleaved compute + epilogue ----
    asm volatile("cp.async.wait_group 0;");
    __syncthreads();
    {
        uint32_t aS = sbase;             // stage 0
        uint32_t bS = aS + 16384;

        uint32_t af[4][2][4];
#pragma unroll
        for (int ks = 0; ks < 4; ks++) {
            uint32_t kx = ((uint32_t)(ks * 32) + hi16) ^ cswz;
#pragma unroll
            for (int mt = 0; mt < 2; mt++)
                asm volatile("ldmatrix.sync.aligned.m8n8.x4.shared.b16 {%0,%1,%2,%3}, [%4];"
                             : "=r"(af[ks][mt][0]), "=r"(af[ks][mt][1]),
                               "=r"(af[ks][mt][2]), "=r"(af[ks][mt][3])
                             : "r"(aS + rbA[mt] + kx));
        }

        float rsum[2][2];
        rsum[0][0] = 0.0f; rsum[0][1] = 0.0f; rsum[1][0] = 0.0f; rsum[1][1] = 0.0f;

#pragma unroll
        for (int np = 0; np < 4; np++) {
#pragma unroll
            for (int ks = 0; ks < 4; ks++) {
                uint32_t kx = ((uint32_t)(ks * 32) + hi16) ^ cswz;
                uint32_t q0, q1, q2, q3;
                asm volatile("ldmatrix.sync.aligned.m8n8.x4.shared.b16 {%0,%1,%2,%3}, [%4];"
                             : "=r"(q0), "=r"(q1), "=r"(q2), "=r"(q3)
                             : "r"(bS + rbB[np] + kx));
#pragma unroll
                for (int mt = 0; mt < 2; mt++) {
                    asm volatile(
                        "mma.sync.aligned.m16n8k16.row.col.f32.bf16.bf16.f32 "
                        "{%0,%1,%2,%3}, {%4,%5,%6,%7}, {%8,%9}, {%0,%1,%2,%3};"
                        : "+f"(acc[mt][2 * np][0]), "+f"(acc[mt][2 * np][1]),
                          "+f"(acc[mt][2 * np][2]), "+f"(acc[mt][2 * np][3])
                        : "r"(af[ks][mt][0]), "r"(af[ks][mt][1]),
                          "r"(af[ks][mt][2]), "r"(af[ks][mt][3]),
                          "r"(q0), "r"(q2));
                    asm volatile(
                        "mma.sync.aligned.m16n8k16.row.col.f32.bf16.bf16.f32 "
                        "{%0,%1,%2,%3}, {%4,%5,%6,%7}, {%8,%9}, {%0,%1,%2,%3};"
                        : "+f"(acc[mt][2 * np + 1][0]), "+f"(acc[mt][2 * np + 1][1]),
                          "+f"(acc[mt][2 * np + 1][2]), "+f"(acc[mt][2 * np + 1][3])
                        : "r"(af[ks][mt][0]), "r"(af[ks][mt][1]),
                          "r"(af[ks][mt][2]), "r"(af[ks][mt][3]),
                          "r"(q1), "r"(q3));
                }
            }
            float csum[2][2];
            csum[0][0] = 0.0f; csum[0][1] = 0.0f; csum[1][0] = 0.0f; csum[1][1] = 0.0f;
#pragma unroll
            for (int mt = 0; mt < 2; mt++)
#pragma unroll
                for (int p = 0; p < 2; p++) {
                    int nt = 2 * np + p;
                    float e0 = ex2_approx(acc[mt][nt][0]);
                    float e1 = ex2_approx(acc[mt][nt][1]);
                    float e2 = ex2_approx(acc[mt][nt][2]);
                    float e3 = ex2_approx(acc[mt][nt][3]);
                    rsum[mt][0] += e0 + e1;
                    rsum[mt][1] += e2 + e3;
                    csum[p][0] += e0 + e2;
                    csum[p][1] += e1 + e3;
                }
#pragma unroll
            for (int p = 0; p < 2; p++)
#pragma unroll
                for (int j = 0; j < 2; j++) {
                    float v = csum[p][j];
                    v += __shfl_xor_sync(0xFFFFFFFFu, v, 4);
                    v += __shfl_xor_sync(0xFFFFFFFFu, v, 8);
                    v += __shfl_xor_sync(0xFFFFFFFFu, v, 16);
                    csum[p][j] = v;
                }
            if (lid < 4) {
                int cb = bj + wc * 64 + np * 16 + lid * 2;
                atomicAdd(&g_colsum[cb + 0], csum[0][0]);
                atomicAdd(&g_colsum[cb + 1], csum[0][1]);
                atomicAdd(&g_colsum[cb + 8], csum[1][0]);
                atomicAdd(&g_colsum[cb + 9], csum[1][1]);
            }
        }

#pragma unroll
        for (int mt = 0; mt < 2; mt++)
#pragma unroll
            for (int h = 0; h < 2; h++) {
                float v = rsum[mt][h];
                v += __shfl_xor_sync(0xFFFFFFFFu, v, 1);
                v += __shfl_xor_sync(0xFFFFFFFFu, v, 2);
                rsum[mt][h] = v;
            }
        if ((lid & 3) == 0) {
            int r = bi + wr * 32 + (lid >> 2);
            atomicAdd(&g_rowsum[r + 0],  rsum[0][0]);
            atomicAdd(&g_rowsum[r + 8],  rsum[0][1]);
            atomicAdd(&g_rowsum[r + 16], rsum[1][0]);
            atomicAdd(&g_rowsum[r + 24], rsum[1][1]);
        }
    }
}

// ---------------- final: tiny reduction over rows ----------------
__global__ void final_kernel(float* __restrict__ out) {
    __shared__ float sred[8];
    int i = blockIdx.x * 256 + threadIdx.x;
    float term = 0.5f * (logf(g_rowsum[i]) + logf(g_colsum[i])) - g_diag[i];
    int lane = threadIdx.x & 31, w = threadIdx.x >> 5;
#pragma unroll
    for (int o = 16; o > 0; o >>= 1) term += __shfl_xor_sync(0xFFFFFFFFu, term, o);
    if (lane == 0) sred[w] = term;
    __syncthreads();
    if (threadIdx.x < 8) {
        float v = sred[threadIdx.x];
#pragma unroll
        for (int o = 4; o > 0; o >>= 1) v += __shfl_xor_sync(0xFFu, v, o);
        if (threadIdx.x == 0) atomicAdd(out, v * (1.0f / NB));
    }
}

extern "C" void kernel_launch(void* const* d_in, const int* in_sizes, int n_in,
                              void* d_out, int out_size) {
    const float* q = (const float*)d_in[0];
    const float* db = (const float*)d_in[1];
    float* out = (float*)d_out;

    static bool attr_set = false;
    if (!attr_set) {
        cudaFuncSetAttribute(gemm_lse_kernel, cudaFuncAttributeMaxDynamicSharedMemorySize, SMEM_DYN);
        attr_set = true;
    }

    dim3 nblk(NB / 16);   // each block: 8 warps x 2 rows = 16 rows
    dim3 nthr(32, 8);
    prep_kernel<<<nblk, nthr>>>(q, db, out);

    dim3 ggrid(NB / 128, NB / 128);
    gemm_lse_kernel<<<ggrid, 256, SMEM_DYN>>>();

    final_kernel<<<NB / 256, 256>>>(out);
}

// round 15
// speedup vs baseline: 1.0015x; 1.0015x over previous
#include <cuda_runtime.h>
#include <cuda_bf16.h>
#include <cstdint>
#include <math.h>

#define NB 16384
#define ND 256

static __device__ __nv_bfloat16 g_qh[NB * ND];  // normalized Q * log2(e)/T, bf16
static __device__ __nv_bfloat16 g_dh[NB * ND];  // normalized D, bf16
static __device__ float g_rowsum[NB];
static __device__ float g_colsum[NB];
static __device__ float g_diag[NB];             // exact fp32 diagonal logits

__device__ __forceinline__ uint32_t smem_u32(const void* p) {
    uint32_t a;
    asm("{ .reg .u64 t; cvta.to.shared.u64 t, %1; cvt.u32.u64 %0, t; }" : "=r"(a) : "l"(p));
    return a;
}
__device__ __forceinline__ float ex2_approx(float x) {
    float r; asm("ex2.approx.f32 %0, %1;" : "=f"(r) : "f"(x)); return r;
}
__device__ __forceinline__ float lg2_approx(float x) {
    float r; asm("lg2.approx.f32 %0, %1;" : "=f"(r) : "f"(x)); return r;
}
__device__ __forceinline__ uint32_t bf2_bits(__nv_bfloat162 v) {
    return *reinterpret_cast<uint32_t*>(&v);
}

// ---------------- prep: normalize q & d, exact diag, zero sums ----------------
// one warp per row; 32B loads, 16B stores per matrix per lane. (best measured)
__global__ void prep_kernel(const float* __restrict__ qin, const float* __restrict__ din,
                            float* __restrict__ out) {
    const float K = 1.4426950408889634f / 0.07f;  // log2(e)/T folded into Q
    int row = blockIdx.x * 8 + threadIdx.y;
    int lane = threadIdx.x;
    const float4* qs = reinterpret_cast<const float4*>(qin + (size_t)row * ND);
    const float4* ds = reinterpret_cast<const float4*>(din + (size_t)row * ND);
    float4 a0 = qs[2 * lane], a1 = qs[2 * lane + 1];
    float4 b0 = ds[2 * lane], b1 = ds[2 * lane + 1];
    float sq = a0.x * a0.x + a0.y * a0.y + a0.z * a0.z + a0.w * a0.w
             + a1.x * a1.x + a1.y * a1.y + a1.z * a1.z + a1.w * a1.w;
    float sd = b0.x * b0.x + b0.y * b0.y + b0.z * b0.z + b0.w * b0.w
             + b1.x * b1.x + b1.y * b1.y + b1.z * b1.z + b1.w * b1.w;
    float dot = a0.x * b0.x + a0.y * b0.y + a0.z * b0.z + a0.w * b0.w
              + a1.x * b1.x + a1.y * b1.y + a1.z * b1.z + a1.w * b1.w;
#pragma unroll
    for (int o = 16; o > 0; o >>= 1) {
        sq  += __shfl_xor_sync(0xFFFFFFFFu, sq, o);
        sd  += __shfl_xor_sync(0xFFFFFFFFu, sd, o);
        dot += __shfl_xor_sync(0xFFFFFFFFu, dot, o);
    }
    float nq = fmaxf(sqrtf(sq), 1e-12f);
    float ndn = fmaxf(sqrtf(sd), 1e-12f);
    float invq = K / nq;
    float invd = 1.0f / ndn;

    uint4 qp, dp;
    qp.x = bf2_bits(__floats2bfloat162_rn(a0.x * invq, a0.y * invq));
    qp.y = bf2_bits(__floats2bfloat162_rn(a0.z * invq, a0.w * invq));
    qp.z = bf2_bits(__floats2bfloat162_rn(a1.x * invq, a1.y * invq));
    qp.w = bf2_bits(__floats2bfloat162_rn(a1.z * invq, a1.w * invq));
    dp.x = bf2_bits(__floats2bfloat162_rn(b0.x * invd, b0.y * invd));
    dp.y = bf2_bits(__floats2bfloat162_rn(b0.z * invd, b0.w * invd));
    dp.z = bf2_bits(__floats2bfloat162_rn(b1.x * invd, b1.y * invd));
    dp.w = bf2_bits(__floats2bfloat162_rn(b1.z * invd, b1.w * invd));
    reinterpret_cast<uint4*>(g_qh + (size_t)row * ND)[lane] = qp;
    reinterpret_cast<uint4*>(g_dh + (size_t)row * ND)[lane] = dp;

    if (lane == 0) {
        g_diag[row] = dot / (nq * ndn) * (1.0f / 0.07f);
        g_rowsum[row] = 0.0f;
        g_colsum[row] = 0.0f;
        if (row == 0) out[0] = 0.0f;
    }
}

// ---------------- fused mma.sync GEMM + exp2 + row/col sums ----------------
// CTA tile 128x128, K chunks of 64, 3-stage cp.async pipeline, one sync/chunk.
// All chunks: A-fragments prefetched for whole chunk, np-major B feed.
// Chunk 3 interleaves the epilogue (all-MUFU exp2) with the MMA stream.
#define STAGE_BYTES 32768
#define SMEM_DYN (3 * STAGE_BYTES)

__global__ void __launch_bounds__(256, 2) gemm_lse_kernel() {
    extern __shared__ char smem[];
    uint32_t sbase = smem_u32(smem);
    int tid = threadIdx.x;
    int wid = tid >> 5, lid = tid & 31;
    int wr = wid & 3, wc = wid >> 2;   // warp tile: rows wr*32..+32, cols wc*64..+64
    int bi = blockIdx.y * 128, bj = blockIdx.x * 128;

    // ---- loader per-thread constants (strength-reduced SW128) ----
    int r0 = tid >> 3;
    int kbl = (tid & 7) * 16;
    uint32_t soff0 = (uint32_t)(r0 * 128 + (kbl ^ ((r0 & 7) << 4)));
    const char* Ag = (const char*)(g_qh + (size_t)bi * ND) + r0 * 512 + kbl;
    const char* Bg = (const char*)(g_dh + (size_t)bj * ND) + r0 * 512 + kbl;

    auto load_chunk = [&](int c, int s) {
        uint32_t sA = sbase + s * STAGE_BYTES + soff0;
        const char* a = Ag + c * 128;
        const char* b = Bg + c * 128;
#pragma unroll
        for (int i = 0; i < 4; i++) {
            asm volatile("cp.async.cg.shared.global [%0], [%1], 16;"
                         :: "r"(sA + i * 4096), "l"(a + i * 16384));
            asm volatile("cp.async.cg.shared.global [%0], [%1], 16;"
                         :: "r"(sA + 16384 + i * 4096), "l"(b + i * 16384));
        }
        asm volatile("cp.async.commit_group;");
    };

    float acc[2][8][4];
#pragma unroll
    for (int mt = 0; mt < 2; mt++)
#pragma unroll
        for (int nt = 0; nt < 8; nt++)
#pragma unroll
            for (int j = 0; j < 4; j++) acc[mt][nt][j] = 0.0f;

    // ---- ldmatrix per-thread constants ----
    int fr = (lid & 7) + ((lid >> 3) & 1) * 8;
    uint32_t cswz = (uint32_t)((lid & 7) << 4);
    uint32_t hi16 = ((lid >> 4) & 1) * 16;
    uint32_t rbA[2], rbB[4];
#pragma unroll
    for (int mt = 0; mt < 2; mt++) rbA[mt] = (uint32_t)((wr * 32 + mt * 16 + fr) * 128);
#pragma unroll
    for (int np = 0; np < 4; np++) rbB[np] = (uint32_t)((wc * 64 + np * 16 + fr) * 128);

    // per-chunk body: prefetch all A frags, then np-major B feed + MMA
#define CHUNK_MMA(aS, bS) do {                                                    \
        uint32_t af[4][2][4];                                                     \
        _Pragma("unroll")                                                         \
        for (int ks = 0; ks < 4; ks++) {                                          \
            uint32_t kx = ((uint32_t)(ks * 32) + hi16) ^ cswz;                    \
            _Pragma("unroll")                                                     \
            for (int mt = 0; mt < 2; mt++)                                        \
                asm volatile("ldmatrix.sync.aligned.m8n8.x4.shared.b16 {%0,%1,%2,%3}, [%4];" \
                             : "=r"(af[ks][mt][0]), "=r"(af[ks][mt][1]),          \
                               "=r"(af[ks][mt][2]), "=r"(af[ks][mt][3])           \
                             : "r"((aS) + rbA[mt] + kx));                         \
        }                                                                         \
        _Pragma("unroll")                                                         \
        for (int np = 0; np < 4; np++) {                                          \
            _Pragma("unroll")                                                     \
            for (int ks = 0; ks < 4; ks++) {                                      \
                uint32_t kx = ((uint32_t)(ks * 32) + hi16) ^ cswz;                \
                uint32_t q0, q1, q2, q3;                                          \
                asm volatile("ldmatrix.sync.aligned.m8n8.x4.shared.b16 {%0,%1,%2,%3}, [%4];" \
                             : "=r"(q0), "=r"(q1), "=r"(q2), "=r"(q3)             \
                             : "r"((bS) + rbB[np] + kx));                         \
                _Pragma("unroll")                                                 \
                for (int mt = 0; mt < 2; mt++) {                                  \
                    asm volatile(                                                 \
                        "mma.sync.aligned.m16n8k16.row.col.f32.bf16.bf16.f32 "    \
                        "{%0,%1,%2,%3}, {%4,%5,%6,%7}, {%8,%9}, {%0,%1,%2,%3};"   \
                        : "+f"(acc[mt][2 * np][0]), "+f"(acc[mt][2 * np][1]),     \
                          "+f"(acc[mt][2 * np][2]), "+f"(acc[mt][2 * np][3])      \
                        : "r"(af[ks][mt][0]), "r"(af[ks][mt][1]),                 \
                          "r"(af[ks][mt][2]), "r"(af[ks][mt][3]),                 \
                          "r"(q0), "r"(q2));                                      \
                    asm volatile(                                                 \
                        "mma.sync.aligned.m16n8k16.row.col.f32.bf16.bf16.f32 "    \
                        "{%0,%1,%2,%3}, {%4,%5,%6,%7}, {%8,%9}, {%0,%1,%2,%3};"   \
                        : "+f"(acc[mt][2 * np + 1][0]), "+f"(acc[mt][2 * np + 1][1]), \
                          "+f"(acc[mt][2 * np + 1][2]), "+f"(acc[mt][2 * np + 1][3]) \
                        : "r"(af[ks][mt][0]), "r"(af[ks][mt][1]),                 \
                          "r"(af[ks][mt][2]), "r"(af[ks][mt][3]),                 \
                          "r"(q1), "r"(q3));                                      \
                }                                                                 \
            }                                                                     \
        }                                                                         \
    } while (0)

    // ---- prologue: fill 3 stages ----
    load_chunk(0, 0);
    load_chunk(1, 1);
    load_chunk(2, 2);

    // ---- chunks 0..2 ----
#pragma unroll
    for (int c = 0; c < 3; c++) {
        if (c == 0) { asm volatile("cp.async.wait_group 2;"); }
        else        { asm volatile("cp.async.wait_group 1;"); }
        __syncthreads();
        if (c == 1) load_chunk(3, 0);

        uint32_t aS = sbase + c * STAGE_BYTES;
        uint32_t bS = aS + 16384;
        CHUNK_MMA(aS, bS);
    }

    // ---- chunk 3: interleaved compute + epilogue ----
    asm volatile("cp.async.wait_group 0;");
    __syncthreads();
    {
        uint32_t aS = sbase;             // stage 0
        uint32_t bS = aS + 16384;

        uint32_t af[4][2][4];
#pragma unroll
        for (int ks = 0; ks < 4; ks++) {
            uint32_t kx = ((uint32_t)(ks * 32) + hi16) ^ cswz;
#pragma unroll
            for (int mt = 0; mt < 2; mt++)
                asm volatile("ldmatrix.sync.aligned.m8n8.x4.shared.b16 {%0,%1,%2,%3}, [%4];"
                             : "=r"(af[ks][mt][0]), "=r"(af[ks][mt][1]),
                               "=r"(af[ks][mt][2]), "=r"(af[ks][mt][3])
                             : "r"(aS + rbA[mt] + kx));
        }

        float rsum[2][2];
        rsum[0][0] = 0.0f; rsum[0][1] = 0.0f; rsum[1][0] = 0.0f; rsum[1][1] = 0.0f;

#pragma unroll
        for (int np = 0; np < 4; np++) {
#pragma unroll
            for (int ks = 0; ks < 4; ks++) {
                uint32_t kx = ((uint32_t)(ks * 32) + hi16) ^ cswz;
                uint32_t q0, q1, q2, q3;
                asm volatile("ldmatrix.sync.aligned.m8n8.x4.shared.b16 {%0,%1,%2,%3}, [%4];"
                             : "=r"(q0), "=r"(q1), "=r"(q2), "=r"(q3)
                             : "r"(bS + rbB[np] + kx));
#pragma unroll
                for (int mt = 0; mt < 2; mt++) {
                    asm volatile(
                        "mma.sync.aligned.m16n8k16.row.col.f32.bf16.bf16.f32 "
                        "{%0,%1,%2,%3}, {%4,%5,%6,%7}, {%8,%9}, {%0,%1,%2,%3};"
                        : "+f"(acc[mt][2 * np][0]), "+f"(acc[mt][2 * np][1]),
                          "+f"(acc[mt][2 * np][2]), "+f"(acc[mt][2 * np][3])
                        : "r"(af[ks][mt][0]), "r"(af[ks][mt][1]),
                          "r"(af[ks][mt][2]), "r"(af[ks][mt][3]),
                          "r"(q0), "r"(q2));
                    asm volatile(
                        "mma.sync.aligned.m16n8k16.row.col.f32.bf16.bf16.f32 "
                        "{%0,%1,%2,%3}, {%4,%5,%6,%7}, {%8,%9}, {%0,%1,%2,%3};"
                        : "+f"(acc[mt][2 * np + 1][0]), "+f"(acc[mt][2 * np + 1][1]),
                          "+f"(acc[mt][2 * np + 1][2]), "+f"(acc[mt][2 * np + 1][3])
                        : "r"(af[ks][mt][0]), "r"(af[ks][mt][1]),
                          "r"(af[ks][mt][2]), "r"(af[ks][mt][3]),
                          "r"(q1), "r"(q3));
                }
            }
            float csum[2][2];
            csum[0][0] = 0.0f; csum[0][1] = 0.0f; csum[1][0] = 0.0f; csum[1][1] = 0.0f;
#pragma unroll
            for (int mt = 0; mt < 2; mt++)
#pragma unroll
                for (int p = 0; p < 2; p++) {
                    int nt = 2 * np + p;
                    float e0 = ex2_approx(acc[mt][nt][0]);
                    float e1 = ex2_approx(acc[mt][nt][1]);
                    float e2 = ex2_approx(acc[mt][nt][2]);
                    float e3 = ex2_approx(acc[mt][nt][3]);
                    rsum[mt][0] += e0 + e1;
                    rsum[mt][1] += e2 + e3;
                    csum[p][0] += e0 + e2;
                    csum[p][1] += e1 + e3;
                }
#pragma unroll
            for (int p = 0; p < 2; p++)
#pragma unroll
                for (int j = 0; j < 2; j++) {
                    float v = csum[p][j];
                    v += __shfl_xor_sync(0xFFFFFFFFu, v, 4);
                    v += __shfl_xor_sync(0xFFFFFFFFu, v, 8);
                    v += __shfl_xor_sync(0xFFFFFFFFu, v, 16);
                    csum[p][j] = v;
                }
            if (lid < 4) {
                int cb = bj + wc * 64 + np * 16 + lid * 2;
                atomicAdd(&g_colsum[cb + 0], csum[0][0]);
                atomicAdd(&g_colsum[cb + 1], csum[0][1]);
                atomicAdd(&g_colsum[cb + 8], csum[1][0]);
                atomicAdd(&g_colsum[cb + 9], csum[1][1]);
            }
        }

#pragma unroll
        for (int mt = 0; mt < 2; mt++)
#pragma unroll
            for (int h = 0; h < 2; h++) {
                float v = rsum[mt][h];
                v += __shfl_xor_sync(0xFFFFFFFFu, v, 1);
                v += __shfl_xor_sync(0xFFFFFFFFu, v, 2);
                rsum[mt][h] = v;
            }
        if ((lid & 3) == 0) {
            int r = bi + wr * 32 + (lid >> 2);
            atomicAdd(&g_rowsum[r + 0],  rsum[0][0]);
            atomicAdd(&g_rowsum[r + 8],  rsum[0][1]);
            atomicAdd(&g_rowsum[r + 16], rsum[1][0]);
            atomicAdd(&g_rowsum[r + 24], rsum[1][1]);
        }
    }
}

// ---------------- final: tiny reduction over rows ----------------
__global__ void final_kernel(float* __restrict__ out) {
    const float LN2 = 0.6931471805599453f;
    __shared__ float sred[8];
    int i = blockIdx.x * 256 + threadIdx.x;
    float term = 0.5f * LN2 * (lg2_approx(g_rowsum[i]) + lg2_approx(g_colsum[i])) - g_diag[i];
    int lane = threadIdx.x & 31, w = threadIdx.x >> 5;
#pragma unroll
    for (int o = 16; o > 0; o >>= 1) term += __shfl_xor_sync(0xFFFFFFFFu, term, o);
    if (lane == 0) sred[w] = term;
    __syncthreads();
    if (threadIdx.x < 8) {
        float v = sred[threadIdx.x];
#pragma unroll
        for (int o = 4; o > 0; o >>= 1) v += __shfl_xor_sync(0xFFu, v, o);
        if (threadIdx.x == 0) atomicAdd(out, v * (1.0f / NB));
    }
}

extern "C" void kernel_launch(void* const* d_in, const int* in_sizes, int n_in,
                              void* d_out, int out_size) {
    const float* q = (const float*)d_in[0];
    const float* db = (const float*)d_in[1];
    float* out = (float*)d_out;

    static bool attr_set = false;
    if (!attr_set) {
        cudaFuncSetAttribute(gemm_lse_kernel, cudaFuncAttributeMaxDynamicSharedMemorySize, SMEM_DYN);
        attr_set = true;
    }

    dim3 nblk(NB / 8);
    dim3 nthr(32, 8);
    prep_kernel<<<nblk, nthr>>>(q, db, out);

    dim3 ggrid(NB / 128, NB / 128);
    gemm_lse_kernel<<<ggrid, 256, SMEM_DYN>>>();

    final_kernel<<<NB / 256, 256>>>(out);
}